// round 10
// baseline (speedup 1.0000x reference)
#include <cuda_runtime.h>
#include <cuda_bf16.h>
#include <stdint.h>
#include <math.h>

#define N_TOT   8192
#define BHALF   4096
#define DD      128
#define NTILE   64                  // 64 x 64 tile grid, tiles 128x128
#define NPAIR   2080                // upper-triangle pairs
// sqrt(2 * log2(e)): Gram entries come out as (sim/T)*log2(e) -> bare ex2
#define SC 1.698644f

// ---- scratch ---------------------------------------------------------------
__device__ uint8_t g_W8[N_TOT * DD];    // e4m3 rows (1 MB)
__device__ float g_pos[N_TOT];
__device__ float g_rowsum[N_TOT];
__device__ unsigned g_ticket;           // zero-init; last CTA resets -> replay-safe

// ---- helpers ---------------------------------------------------------------
__device__ __forceinline__ uint32_t smem_u32(const void* p) {
    uint32_t a;
    asm("{ .reg .u64 t; cvta.to.shared.u64 t, %1; cvt.u32.u64 %0, t; }" : "=r"(a) : "l"(p));
    return a;
}
__device__ __forceinline__ float ex2f(float x) {
    float y; asm("ex2.approx.f32 %0, %1;" : "=f"(y) : "f"(x)); return y;
}
__device__ __forceinline__ void ldsm_x4(uint32_t* r, uint32_t addr) {
    asm volatile("ldmatrix.sync.aligned.m8n8.x4.shared.b16 {%0,%1,%2,%3}, [%4];"
                 : "=r"(r[0]), "=r"(r[1]), "=r"(r[2]), "=r"(r[3]) : "r"(addr));
}
// fp8 e4m3 MMA, K=32 per instruction
__device__ __forceinline__ void mma16832(float* c, const uint32_t* a, uint32_t b0, uint32_t b1) {
    asm volatile("mma.sync.aligned.m16n8k32.row.col.f32.e4m3.e4m3.f32 "
                 "{%0,%1,%2,%3}, {%4,%5,%6,%7}, {%8,%9}, {%0,%1,%2,%3};"
                 : "+f"(c[0]), "+f"(c[1]), "+f"(c[2]), "+f"(c[3])
                 : "r"(a[0]), "r"(a[1]), "r"(a[2]), "r"(a[3]), "r"(b0), "r"(b1));
}
#define CP_COMMIT() asm volatile("cp.async.commit_group;" ::: "memory")
#define CP_WAIT0()  asm volatile("cp.async.wait_group 0;" ::: "memory")

// 128 rows x 128 bytes fp8 tile, 16B-chunk XOR swizzle (8 chunks/row)
__device__ __forceinline__ void cp_tile(uint32_t dstBase, int gRow, int tid) {
    const char* src = (const char*)g_W8 + (size_t)gRow * 128;
    #pragma unroll
    for (int i = 0; i < 4; ++i) {
        int idx = tid + i * 256;
        int row = idx >> 3, c = idx & 7;
        uint32_t d = dstBase + row * 128 + ((c ^ (row & 7)) << 4);
        const char* s = src + row * 128 + c * 16;
        asm volatile("cp.async.cg.shared.global [%0], [%1], 16;" :: "r"(d), "l"(s) : "memory");
    }
}

__device__ __forceinline__ int cumC(int I) { return NTILE * I - (I * (I - 1)) / 2; }

// ---------------------------------------------------------------------------
// Kernel 1: normalize (log2-domain scale) -> e4m3, positive pairs, zero rowsum.
// ---------------------------------------------------------------------------
__global__ void __launch_bounds__(256) k_normpos(const float* __restrict__ zi,
                                                 const float* __restrict__ zj) {
    int gtid = blockIdx.x * 256 + threadIdx.x;
    if (gtid < N_TOT) g_rowsum[gtid] = 0.0f;

    int warp = threadIdx.x >> 5, lane = threadIdx.x & 31;
    int r = blockIdx.x * 8 + warp;                 // 0..4095
    float4 a = reinterpret_cast<const float4*>(zi + (size_t)r * DD)[lane];
    float4 b = reinterpret_cast<const float4*>(zj + (size_t)r * DD)[lane];
    float aa = a.x * a.x + a.y * a.y + a.z * a.z + a.w * a.w;
    float bb = b.x * b.x + b.y * b.y + b.z * b.z + b.w * b.w;
    float ab = a.x * b.x + a.y * b.y + a.z * b.z + a.w * b.w;
    #pragma unroll
    for (int o = 16; o; o >>= 1) {
        aa += __shfl_xor_sync(0xFFFFFFFFu, aa, o);
        bb += __shfl_xor_sync(0xFFFFFFFFu, bb, o);
        ab += __shfl_xor_sync(0xFFFFFFFFu, ab, o);
    }
    float na = fmaxf(sqrtf(aa), 1e-8f), nb = fmaxf(sqrtf(bb), 1e-8f);
    float sa = SC / na, sb2 = SC / nb;

    uint16_t lo, hi;
    asm("cvt.rn.satfinite.e4m3x2.f32 %0, %1, %2;" : "=h"(lo) : "f"(a.y * sa), "f"(a.x * sa));
    asm("cvt.rn.satfinite.e4m3x2.f32 %0, %1, %2;" : "=h"(hi) : "f"(a.w * sa), "f"(a.z * sa));
    reinterpret_cast<uint32_t*>(g_W8 + (size_t)r * DD)[lane] = (uint32_t)lo | ((uint32_t)hi << 16);
    asm("cvt.rn.satfinite.e4m3x2.f32 %0, %1, %2;" : "=h"(lo) : "f"(b.y * sb2), "f"(b.x * sb2));
    asm("cvt.rn.satfinite.e4m3x2.f32 %0, %1, %2;" : "=h"(hi) : "f"(b.w * sb2), "f"(b.z * sb2));
    reinterpret_cast<uint32_t*>(g_W8 + (size_t)(r + BHALF) * DD)[lane] = (uint32_t)lo | ((uint32_t)hi << 16);

    if (lane == 0) {
        float p = 2.0f * ab / (na * nb);
        g_pos[r] = p;
        g_pos[r + BHALF] = p;
    }
}

// ---------------------------------------------------------------------------
// Kernel 2: symmetric FP8 HMMA Gram. One 128x128 tile pair (I<=J) per CTA.
// ---------------------------------------------------------------------------
extern __shared__ char smem_g[];

__global__ void __launch_bounds__(256, 2) k_gemm(float* __restrict__ out) {
    uint32_t sA = smem_u32(smem_g);
    uint32_t sB = sA + 16384;

    int tid = threadIdx.x, lane = tid & 31, wid = tid >> 5;
    int warpM = wid >> 2, warpN = wid & 3;

    // pair id -> (I, J), I <= J
    int p = blockIdx.x;
    int I = (int)(64.5f - sqrtf(fmaxf(64.5f * 64.5f - 2.0f * (float)p, 0.0f)));
    while (cumC(I + 1) <= p) ++I;
    while (cumC(I) > p) --I;
    int J = I + (p - cumC(I));
    bool diag = (I == J);
    int rowBase = I * 128, colBase = J * 128;

    cp_tile(sA, rowBase, tid);
    cp_tile(sB, colBase, tid);
    CP_COMMIT();
    CP_WAIT0();
    __syncthreads();

    // fp8 m16n8k32 fragment lane patterns (16-byte k-halves)
    int aRow  = warpM * 64 + (lane & 15);            // + mi*16
    int aKc   = (lane >> 4);                          // k-half chunk (0/1)
    int bJ    = warpN * 32 + (lane & 7) + ((lane >> 4) << 3);  // + nj*16
    int bKc   = (lane >> 3) & 1;                      // k-half chunk

    float c[4][4][4];
    #pragma unroll
    for (int mi = 0; mi < 4; ++mi)
        #pragma unroll
        for (int nf = 0; nf < 4; ++nf)
            #pragma unroll
            for (int q = 0; q < 4; ++q) c[mi][nf][q] = 0.f;

    #pragma unroll
    for (int ks = 0; ks < 4; ++ks) {                  // K = 4 x 32
        uint32_t a[4][4], b[2][4];
        #pragma unroll
        for (int mi = 0; mi < 4; ++mi) {
            int r = aRow + mi * 16;
            int ch = ks * 2 + aKc;
            ldsm_x4(a[mi], sA + r * 128 + (((ch) ^ (r & 7)) << 4));
        }
        #pragma unroll
        for (int nj = 0; nj < 2; ++nj) {
            int j = bJ + nj * 16;
            int ch = ks * 2 + bKc;
            ldsm_x4(b[nj], sB + j * 128 + (((ch) ^ (j & 7)) << 4));
        }
        #pragma unroll
        for (int mi = 0; mi < 4; ++mi) {
            mma16832(c[mi][0], a[mi], b[0][0], b[0][1]);
            mma16832(c[mi][1], a[mi], b[0][2], b[0][3]);
            mma16832(c[mi][2], a[mi], b[1][0], b[1][1]);
            mma16832(c[mi][3], a[mi], b[1][2], b[1][3]);
        }
    }
    __syncthreads();                     // ldsm done -> smem reusable

    // exp2 in place; diagonal masked by zeroing
    #pragma unroll
    for (int mi = 0; mi < 4; ++mi)
        #pragma unroll
        for (int nf = 0; nf < 4; ++nf)
            #pragma unroll
            for (int q = 0; q < 4; ++q) c[mi][nf][q] = ex2f(c[mi][nf][q]);

    if (diag) {
        int colT = colBase + warpN * 32 + (lane & 3) * 2;
        int rT = rowBase + warpM * 64 + (lane >> 2);
        #pragma unroll
        for (int mi = 0; mi < 4; ++mi) {
            int r0 = rT + mi * 16, r1 = r0 + 8;
            #pragma unroll
            for (int nf = 0; nf < 4; ++nf) {
                int c0 = colT + nf * 8;
                if (c0 == r0)     c[mi][nf][0] = 0.f;
                if (c0 + 1 == r0) c[mi][nf][1] = 0.f;
                if (c0 == r1)     c[mi][nf][2] = 0.f;
                if (c0 + 1 == r1) c[mi][nf][3] = 0.f;
            }
        }
    }

    // ---- row sums -> block I ----
    float* sRed = (float*)smem_g;        // [128][17]
    #pragma unroll
    for (int mi = 0; mi < 4; ++mi) {
        float s0 = 0.f, s1 = 0.f;
        #pragma unroll
        for (int nf = 0; nf < 4; ++nf) {
            s0 += c[mi][nf][0] + c[mi][nf][1];
            s1 += c[mi][nf][2] + c[mi][nf][3];
        }
        int r = warpM * 64 + mi * 16 + (lane >> 2);
        sRed[r * 17 + warpN * 4 + (lane & 3)] = s0;
        sRed[(r + 8) * 17 + warpN * 4 + (lane & 3)] = s1;
    }
    __syncthreads();
    if (tid < 128) {
        float s = 0.0f;
        #pragma unroll
        for (int j = 0; j < 16; ++j) s += sRed[tid * 17 + j];
        atomicAdd(&g_rowsum[rowBase + tid], s);
    }

    // ---- column sums -> block J (off-diagonal only) ----
    if (!diag) {
        float* sCol = (float*)(smem_g + 8704);   // [2][128]
        #pragma unroll
        for (int nf = 0; nf < 4; ++nf) {
            float s0 = 0.f, s1 = 0.f;
            #pragma unroll
            for (int mi = 0; mi < 4; ++mi) {
                s0 += c[mi][nf][0] + c[mi][nf][2];
                s1 += c[mi][nf][1] + c[mi][nf][3];
            }
            #pragma unroll
            for (int o = 4; o <= 16; o <<= 1) {
                s0 += __shfl_xor_sync(0xFFFFFFFFu, s0, o);
                s1 += __shfl_xor_sync(0xFFFFFFFFu, s1, o);
            }
            if (lane < 4) {
                int col = warpN * 32 + nf * 8 + lane * 2;
                sCol[warpM * 128 + col]     = s0;
                sCol[warpM * 128 + col + 1] = s1;
            }
        }
        __syncthreads();
        if (tid < 128)
            atomicAdd(&g_rowsum[colBase + tid], sCol[tid] + sCol[128 + tid]);
    }
    __syncthreads();

    // ---- last-CTA final reduction ----
    volatile unsigned* flag = (volatile unsigned*)(smem_g + 12288);
    if (tid == 0) {
        __threadfence();
        unsigned v = atomicAdd(&g_ticket, 1u);
        *flag = (v == (NPAIR - 1)) ? 1u : 0u;
    }
    __syncthreads();
    if (*flag) {
        float acc = 0.0f;
        for (int i = tid; i < N_TOT; i += 256)
            acc += __logf(__ldcg(&g_rowsum[i])) - g_pos[i];
        #pragma unroll
        for (int o = 16; o; o >>= 1) acc += __shfl_xor_sync(0xFFFFFFFFu, acc, o);
        float* wsum = (float*)(smem_g + 12352);
        if (lane == 0) wsum[wid] = acc;
        __syncthreads();
        if (tid == 0) {
            float tot = 0.f;
            #pragma unroll
            for (int w = 0; w < 8; ++w) tot += wsum[w];
            out[0] = tot * (1.0f / (float)N_TOT);
            g_ticket = 0u;               // reset for graph replay
        }
    }
}

// ---------------------------------------------------------------------------
extern "C" void kernel_launch(void* const* d_in, const int* in_sizes, int n_in,
                              void* d_out, int out_size) {
    const float* zi = (const float*)d_in[0];
    const float* zj = (const float*)d_in[1];
    float* out = (float*)d_out;

    cudaFuncSetAttribute(k_gemm, cudaFuncAttributeMaxDynamicSharedMemorySize, 32768);

    k_normpos<<<BHALF / 8, 256>>>(zi, zj);
    k_gemm<<<NPAIR, 256, 32768>>>(out);
}

// round 11
// speedup vs baseline: 1.1156x; 1.1156x over previous
#include <cuda_runtime.h>
#include <cuda_bf16.h>
#include <stdint.h>
#include <math.h>

#define N_TOT   8192
#define BHALF   4096
#define DD      128
#define NTILE   64                  // 64 x 64 grid of 128x128 tiles
#define NPAIR   2080                // upper-triangle pairs
#define NCTA    1040                // 2 pairs per CTA
// sqrt(2 * log2(e)): Gram entries come out as (sim/T)*log2(e) -> bare ex2
#define SC 1.698644f

// ---- scratch ---------------------------------------------------------------
__device__ __nv_bfloat16 g_Wb[N_TOT * DD];
__device__ float g_pos[N_TOT];
__device__ float g_rowsum[N_TOT];
__device__ unsigned g_ticket;           // zero-init; last CTA resets -> replay-safe

// ---- smem layout -----------------------------------------------------------
#define SM_A     0
#define SM_B0    32768
#define SM_B1    65536
#define SM_RED   98304                  // [128][17] floats = 8704 B
#define SM_COL   107008                 // [2][128] floats = 1024 B
#define SM_FLAG  108032
#define SM_WSUM  108096
#define SM_TOTAL 108160

// ---- helpers ---------------------------------------------------------------
__device__ __forceinline__ uint32_t smem_u32(const void* p) {
    uint32_t a;
    asm("{ .reg .u64 t; cvta.to.shared.u64 t, %1; cvt.u32.u64 %0, t; }" : "=r"(a) : "l"(p));
    return a;
}
__device__ __forceinline__ float ex2f(float x) {
    float y; asm("ex2.approx.f32 %0, %1;" : "=f"(y) : "f"(x)); return y;
}
__device__ __forceinline__ void ldsm_x4(uint32_t* r, uint32_t addr) {
    asm volatile("ldmatrix.sync.aligned.m8n8.x4.shared.b16 {%0,%1,%2,%3}, [%4];"
                 : "=r"(r[0]), "=r"(r[1]), "=r"(r[2]), "=r"(r[3]) : "r"(addr));
}
__device__ __forceinline__ void mma16816(float* c, const uint32_t* a, uint32_t b0, uint32_t b1) {
    asm volatile("mma.sync.aligned.m16n8k16.row.col.f32.bf16.bf16.f32 "
                 "{%0,%1,%2,%3}, {%4,%5,%6,%7}, {%8,%9}, {%0,%1,%2,%3};"
                 : "+f"(c[0]), "+f"(c[1]), "+f"(c[2]), "+f"(c[3])
                 : "r"(a[0]), "r"(a[1]), "r"(a[2]), "r"(a[3]), "r"(b0), "r"(b1));
}
#define CP_COMMIT() asm volatile("cp.async.commit_group;" ::: "memory")
#define CP_WAIT0()  asm volatile("cp.async.wait_group 0;" ::: "memory")
#define CP_WAIT1()  asm volatile("cp.async.wait_group 1;" ::: "memory")

// 128 rows x 256B bf16 tile, 16B-chunk XOR swizzle (16 chunks/row)
__device__ __forceinline__ void cp_tile(uint32_t dstBase, int gRow, int tid) {
    const char* src = (const char*)g_Wb + (size_t)gRow * 256;
    #pragma unroll
    for (int i = 0; i < 8; ++i) {
        int idx = tid + i * 256;
        int row = idx >> 4, c = idx & 15;
        uint32_t d = dstBase + row * 256 + ((c ^ (row & 7)) << 4);
        const char* s = src + row * 256 + c * 16;
        asm volatile("cp.async.cg.shared.global [%0], [%1], 16;" :: "r"(d), "l"(s) : "memory");
    }
}

__device__ __forceinline__ int cumC(int I) { return NTILE * I - (I * (I - 1)) / 2; }

// ---------------------------------------------------------------------------
// Kernel 1: normalize (log2-domain scale) -> bf16, positive pairs, zero rowsum.
// ---------------------------------------------------------------------------
__global__ void __launch_bounds__(256) k_normpos(const float* __restrict__ zi,
                                                 const float* __restrict__ zj) {
    int gtid = blockIdx.x * 256 + threadIdx.x;
    if (gtid < N_TOT) g_rowsum[gtid] = 0.0f;

    int warp = threadIdx.x >> 5, lane = threadIdx.x & 31;
    int r = blockIdx.x * 8 + warp;                 // 0..4095
    float4 a = reinterpret_cast<const float4*>(zi + (size_t)r * DD)[lane];
    float4 b = reinterpret_cast<const float4*>(zj + (size_t)r * DD)[lane];
    float aa = a.x * a.x + a.y * a.y + a.z * a.z + a.w * a.w;
    float bb = b.x * b.x + b.y * b.y + b.z * b.z + b.w * b.w;
    float ab = a.x * b.x + a.y * b.y + a.z * b.z + a.w * b.w;
    #pragma unroll
    for (int o = 16; o; o >>= 1) {
        aa += __shfl_xor_sync(0xFFFFFFFFu, aa, o);
        bb += __shfl_xor_sync(0xFFFFFFFFu, bb, o);
        ab += __shfl_xor_sync(0xFFFFFFFFu, ab, o);
    }
    float na = fmaxf(sqrtf(aa), 1e-8f), nb = fmaxf(sqrtf(bb), 1e-8f);
    float sa = SC / na, sb2 = SC / nb;
    __nv_bfloat162 p0 = __floats2bfloat162_rn(a.x * sa, a.y * sa);
    __nv_bfloat162 p1 = __floats2bfloat162_rn(a.z * sa, a.w * sa);
    uint2 oa; oa.x = *(uint32_t*)&p0; oa.y = *(uint32_t*)&p1;
    reinterpret_cast<uint2*>(g_Wb + (size_t)r * DD)[lane] = oa;
    __nv_bfloat162 q0 = __floats2bfloat162_rn(b.x * sb2, b.y * sb2);
    __nv_bfloat162 q1 = __floats2bfloat162_rn(b.z * sb2, b.w * sb2);
    uint2 ob; ob.x = *(uint32_t*)&q0; ob.y = *(uint32_t*)&q1;
    reinterpret_cast<uint2*>(g_Wb + (size_t)(r + BHALF) * DD)[lane] = ob;
    if (lane == 0) {
        float p = 2.0f * ab / (na * nb);
        g_pos[r] = p;
        g_pos[r + BHALF] = p;
    }
}

// ---------------------------------------------------------------------------
// Kernel 2: symmetric bf16 HMMA Gram, TWO 128x128 tile pairs per CTA.
// A row-tile reused across both pairs (except at row boundaries); B double-buffered.
// ---------------------------------------------------------------------------
extern __shared__ char smem_g[];

__global__ void __launch_bounds__(256, 2) k_gemm(float* __restrict__ out) {
    uint32_t sb = smem_u32(smem_g);
    int tid = threadIdx.x, lane = tid & 31, wid = tid >> 5;
    int warpM = wid >> 2, warpN = wid & 3;

    // pair ids p0 = 2*bid, p1 = p0+1 -> (I0,J0), (I1,J1)
    int p = blockIdx.x * 2;
    int I0 = (int)(64.5f - sqrtf(fmaxf(64.5f * 64.5f - 2.0f * (float)p, 0.0f)));
    while (cumC(I0 + 1) <= p) ++I0;
    while (cumC(I0) > p) --I0;
    int J0 = I0 + (p - cumC(I0));
    int I1 = I0, J1 = J0 + 1;
    if (J1 == NTILE) { I1 = I0 + 1; J1 = I1; }

    // loads: group0 = {A(I0), B(J0)}, group1 = {B(J1)}
    cp_tile(sb + SM_A, I0 * 128, tid);
    cp_tile(sb + SM_B0, J0 * 128, tid);
    CP_COMMIT();
    cp_tile(sb + SM_B1, J1 * 128, tid);
    CP_COMMIT();
    CP_WAIT1();                          // A0 + B0 ready; B1 may be in flight
    __syncthreads();

    // fragment lane patterns
    int aRow = lane & 15;
    int aK   = (lane >> 4) << 3;
    int bJ   = (lane & 7) + ((lane >> 4) << 3);
    int bK   = ((lane >> 3) & 1) << 3;
    int aRowG = warpM * 64 + aRow;
    int bJG   = warpN * 32 + bJ;

    float* sRed = (float*)(smem_g + SM_RED);
    float* sCol = (float*)(smem_g + SM_COL);

    float c[4][4][4];

    #pragma unroll 1
    for (int q = 0; q < 2; ++q) {
        int I = q ? I1 : I0;
        int J = q ? J1 : J0;
        bool diag = (I == J);
        int rowBase = I * 128, colBase = J * 128;
        uint32_t cb = sb + (q ? SM_B1 : SM_B0);

        if (q == 1) {
            // all warps are past pair-0 epilogue (trailing sync) -> sA reusable
            if (I1 != I0) { cp_tile(sb + SM_A, I1 * 128, tid); CP_COMMIT(); }
            CP_WAIT0();
            __syncthreads();
        }

        #pragma unroll
        for (int mi = 0; mi < 4; ++mi)
            #pragma unroll
            for (int nf = 0; nf < 4; ++nf)
                #pragma unroll
                for (int qq = 0; qq < 4; ++qq) c[mi][nf][qq] = 0.f;

        #pragma unroll
        for (int ks = 0; ks < 8; ++ks) {
            uint32_t a[4][4], b[2][4];
            #pragma unroll
            for (int mi = 0; mi < 4; ++mi) {
                int r = aRowG + mi * 16;
                int k = ks * 16 + aK;
                ldsm_x4(a[mi], sb + SM_A + r * 256 + (((k >> 3) ^ (r & 7)) << 4));
            }
            #pragma unroll
            for (int nj = 0; nj < 2; ++nj) {
                int j = bJG + nj * 16;
                int k = ks * 16 + bK;
                ldsm_x4(b[nj], cb + j * 256 + (((k >> 3) ^ (j & 7)) << 4));
            }
            #pragma unroll
            for (int mi = 0; mi < 4; ++mi) {
                mma16816(c[mi][0], a[mi], b[0][0], b[0][1]);
                mma16816(c[mi][1], a[mi], b[0][2], b[0][3]);
                mma16816(c[mi][2], a[mi], b[1][0], b[1][1]);
                mma16816(c[mi][3], a[mi], b[1][2], b[1][3]);
            }
        }

        // exp2 in place; diagonal masked by zeroing
        #pragma unroll
        for (int mi = 0; mi < 4; ++mi)
            #pragma unroll
            for (int nf = 0; nf < 4; ++nf)
                #pragma unroll
                for (int qq = 0; qq < 4; ++qq) c[mi][nf][qq] = ex2f(c[mi][nf][qq]);

        if (diag) {
            int colT = colBase + warpN * 32 + (lane & 3) * 2;
            int rT = rowBase + warpM * 64 + (lane >> 2);
            #pragma unroll
            for (int mi = 0; mi < 4; ++mi) {
                int r0 = rT + mi * 16, r1 = r0 + 8;
                #pragma unroll
                for (int nf = 0; nf < 4; ++nf) {
                    int c0 = colT + nf * 8;
                    if (c0 == r0)     c[mi][nf][0] = 0.f;
                    if (c0 + 1 == r0) c[mi][nf][1] = 0.f;
                    if (c0 == r1)     c[mi][nf][2] = 0.f;
                    if (c0 + 1 == r1) c[mi][nf][3] = 0.f;
                }
            }
        }

        // ---- row sums -> block I ----
        #pragma unroll
        for (int mi = 0; mi < 4; ++mi) {
            float s0 = 0.f, s1 = 0.f;
            #pragma unroll
            for (int nf = 0; nf < 4; ++nf) {
                s0 += c[mi][nf][0] + c[mi][nf][1];
                s1 += c[mi][nf][2] + c[mi][nf][3];
            }
            int r = warpM * 64 + mi * 16 + (lane >> 2);
            sRed[r * 17 + warpN * 4 + (lane & 3)] = s0;
            sRed[(r + 8) * 17 + warpN * 4 + (lane & 3)] = s1;
        }
        __syncthreads();
        if (tid < 128) {
            float s = 0.0f;
            #pragma unroll
            for (int j = 0; j < 16; ++j) s += sRed[tid * 17 + j];
            atomicAdd(&g_rowsum[rowBase + tid], s);
        }

        // ---- column sums -> block J (off-diagonal only) ----
        if (!diag) {
            #pragma unroll
            for (int nf = 0; nf < 4; ++nf) {
                float s0 = 0.f, s1 = 0.f;
                #pragma unroll
                for (int mi = 0; mi < 4; ++mi) {
                    s0 += c[mi][nf][0] + c[mi][nf][2];
                    s1 += c[mi][nf][1] + c[mi][nf][3];
                }
                #pragma unroll
                for (int o = 4; o <= 16; o <<= 1) {
                    s0 += __shfl_xor_sync(0xFFFFFFFFu, s0, o);
                    s1 += __shfl_xor_sync(0xFFFFFFFFu, s1, o);
                }
                if (lane < 4) {
                    int col = warpN * 32 + nf * 8 + lane * 2;
                    sCol[warpM * 128 + col]     = s0;
                    sCol[warpM * 128 + col + 1] = s1;
                }
            }
            __syncthreads();
            if (tid < 128)
                atomicAdd(&g_rowsum[colBase + tid], sCol[tid] + sCol[128 + tid]);
        }
        __syncthreads();                 // sRed/sCol (and sA for q=1) safe to reuse
    }

    // ---- last-CTA final reduction ----
    volatile unsigned* flag = (volatile unsigned*)(smem_g + SM_FLAG);
    if (tid == 0) {
        __threadfence();
        unsigned v = atomicAdd(&g_ticket, 1u);
        *flag = (v == (NCTA - 1)) ? 1u : 0u;
    }
    __syncthreads();
    if (*flag) {
        float acc = 0.0f;
        for (int i = tid; i < N_TOT; i += 256)
            acc += __logf(__ldcg(&g_rowsum[i])) - g_pos[i];
        #pragma unroll
        for (int o = 16; o; o >>= 1) acc += __shfl_xor_sync(0xFFFFFFFFu, acc, o);
        float* wsum = (float*)(smem_g + SM_WSUM);
        if (lane == 0) wsum[wid] = acc;
        __syncthreads();
        if (tid == 0) {
            float tot = 0.f;
            #pragma unroll
            for (int w = 0; w < 8; ++w) tot += wsum[w];
            out[0] = tot * (1.0f / (float)N_TOT);
            g_ticket = 0u;               // reset for graph replay
        }
    }
}

// ---------------------------------------------------------------------------
extern "C" void kernel_launch(void* const* d_in, const int* in_sizes, int n_in,
                              void* d_out, int out_size) {
    const float* zi = (const float*)d_in[0];
    const float* zj = (const float*)d_in[1];
    float* out = (float*)d_out;

    cudaFuncSetAttribute(k_gemm, cudaFuncAttributeMaxDynamicSharedMemorySize, SM_TOTAL);

    k_normpos<<<BHALF / 8, 256>>>(zi, zj);
    k_gemm<<<NCTA, 256, SM_TOTAL>>>(out);
}